// round 14
// baseline (speedup 1.0000x reference)
#include <cuda_runtime.h>
#include <math_constants.h>
#include <cstdint>

// Problem constants: B=16,T=2048,D=256,K=4096
#define N_TOK 32768
#define DIM   256
#define KCB   4096
#define NKCH  (DIM / 4)     // 64 packed int32 k-chunks per row

#define TOK_TILE  128
#define CODE_TILE 128
#define N_QUART   8                        // code-range slices per token tile
#define QRANGE    (KCB / N_QUART)          // 512 codes per CTA
#define N_CTILE   (QRANGE / CODE_TILE)     // 4 tiles per CTA
#define MAX_CAND  256

// ---------------- device scratch (no allocations allowed) -------------------
__device__ float  g_S[N_TOK];
__device__ float  g_c[KCB];
__device__ float2 g_sec[KCB];              // {-2*se, c} for coarse epilogue
__device__ float  g_loss[N_TOK];
__device__ double g_part[128];
__device__ float  g_sx[N_TOK], g_Lx[N_TOK];
__device__ unsigned g_maxse_u, g_maxLe_u;  // raw bits of positive floats (monotone)
__device__ __align__(16) int g_XqT[NKCH * N_TOK];   // [kchunk][token]  8MB
__device__ __align__(16) int g_EqT[NKCH * KCB];     // [kchunk][code]   1MB
__device__ unsigned short g_cand[N_TOK][MAX_CAND];  // 16MB
__device__ float  g_cand_s[N_TOK][MAX_CAND];        // 32MB coarse scores
__device__ int    g_ncand[N_TOK];

// ---------------- helpers ----------------------------------------------------
__device__ __forceinline__ uint32_t smem_to_u32(const void* p) {
    uint32_t a;
    asm("{ .reg .u64 t; cvta.to.shared.u64 t, %1; cvt.u32.u64 %0, t; }" : "=r"(a) : "l"(p));
    return a;
}
__device__ __forceinline__ void dp4a(int& acc, int a, int b) {
    asm("dp4a.s32.s32 %0, %1, %2, %0;" : "+r"(acc) : "r"(a), "r"(b));
}
__device__ __forceinline__ void cp_async16(uint32_t dst_smem, const void* src) {
    asm volatile("cp.async.cg.shared.global [%0], [%1], 16;" :: "r"(dst_smem), "l"(src) : "memory");
}
__device__ __forceinline__ void cp_commit() { asm volatile("cp.async.commit_group;" ::: "memory"); }
__device__ __forceinline__ void cp_wait0()  { asm volatile("cp.async.wait_group 0;"  ::: "memory"); }
__device__ __forceinline__ int q8(float v, float inv) {
    int q = __float2int_rn(v * inv);
    return max(-127, min(127, q));
}
// order-preserving encode for floats (any sign) -> u32
__device__ __forceinline__ uint32_t fenc(float f) {
    uint32_t u = __float_as_uint(f);
    return (u & 0x80000000u) ? ~u : (u | 0x80000000u);
}
__device__ __forceinline__ float fdec(uint32_t u) {
    uint32_t b = (u & 0x80000000u) ? (u & 0x7FFFFFFFu) : ~u;
    return __uint_as_float(b);
}
__device__ __forceinline__ uint32_t warp_min_u32(uint32_t v) {
    uint32_t r;
    asm volatile("redux.sync.min.u32 %0, %1, 0xffffffff;" : "=r"(r) : "r"(v));
    return r;
}
// rigorous per-token margin: 2*(int8 quant bound on 2m) + fp32 d2-chain slop
__device__ __forceinline__ float token_margin(float sx, float lx, float mse, float mle) {
    return 2.0f * (0.5f * sx * mle + 0.5f * mse * lx + 128.0f * sx * mse) + 3.0e-4f;
}

// ---------------------------------------------------------------------------
// Kernel 1: per-row exact-fp32 sums of squares (bit-matching R2 chain),
// per-row max/L1, int8 quantization into TRANSPOSED packed layout.
// Also builds g_sec and global maxima of se/Le (warp-reduce + atomicMax;
// max is idempotent across graph replays => deterministic).
// ---------------------------------------------------------------------------
__global__ void prep_kernel(const float* __restrict__ X, const float* __restrict__ E) {
    int i = blockIdx.x * blockDim.x + threadIdx.x;
    if (i < N_TOK) {
        g_ncand[i] = 0;
        const float4* row = reinterpret_cast<const float4*>(X + (size_t)i * DIM);
        float s = 0.0f, mx = 0.0f, l1 = 0.0f;
        #pragma unroll 8
        for (int j = 0; j < DIM / 4; j++) {
            float4 v = row[j];
            s = __fadd_rn(s, __fmul_rn(v.x, v.x));
            s = __fadd_rn(s, __fmul_rn(v.y, v.y));
            s = __fadd_rn(s, __fmul_rn(v.z, v.z));
            s = __fadd_rn(s, __fmul_rn(v.w, v.w));
            float ax = fabsf(v.x), ay = fabsf(v.y), az = fabsf(v.z), aw = fabsf(v.w);
            mx = fmaxf(fmaxf(mx, ax), fmaxf(ay, fmaxf(az, aw)));
            l1 += ax + ay + az + aw;
        }
        g_S[i] = s;
        mx = fmaxf(mx, 1e-30f);
        float inv = 127.0f / mx;
        g_sx[i] = mx / 127.0f;
        g_Lx[i] = l1;
        #pragma unroll 8
        for (int k = 0; k < NKCH; k++) {
            float4 v = row[k];
            int q0 = q8(v.x, inv), q1 = q8(v.y, inv), q2 = q8(v.z, inv), q3 = q8(v.w, inv);
            g_XqT[k * N_TOK + i] = (q0 & 255) | ((q1 & 255) << 8) | ((q2 & 255) << 16) | ((q3 & 255) << 24);
        }
    }
    if (i < KCB) {
        const float4* row = reinterpret_cast<const float4*>(E + (size_t)i * DIM);
        float s = 0.0f, mx = 0.0f, l1 = 0.0f;
        #pragma unroll 8
        for (int j = 0; j < DIM / 4; j++) {
            float4 v = row[j];
            s = __fadd_rn(s, __fmul_rn(v.x, v.x));
            s = __fadd_rn(s, __fmul_rn(v.y, v.y));
            s = __fadd_rn(s, __fmul_rn(v.z, v.z));
            s = __fadd_rn(s, __fmul_rn(v.w, v.w));
            float ax = fabsf(v.x), ay = fabsf(v.y), az = fabsf(v.z), aw = fabsf(v.w);
            mx = fmaxf(fmaxf(mx, ax), fmaxf(ay, fmaxf(az, aw)));
            l1 += ax + ay + az + aw;
        }
        g_c[i] = s;
        mx = fmaxf(mx, 1e-30f);
        float inv = 127.0f / mx;
        float se = mx / 127.0f;
        g_sec[i] = make_float2(-2.0f * se, s);
        // global maxima (positive floats: raw bits monotone as u32)
        unsigned wse = __reduce_max_sync(0xffffffffu, __float_as_uint(se));
        unsigned wle = __reduce_max_sync(0xffffffffu, __float_as_uint(l1));
        if ((threadIdx.x & 31) == 0) {
            atomicMax(&g_maxse_u, wse);
            atomicMax(&g_maxLe_u, wle);
        }
        #pragma unroll 8
        for (int k = 0; k < NKCH; k++) {
            float4 v = row[k];
            int q0 = q8(v.x, inv), q1 = q8(v.y, inv), q2 = q8(v.z, inv), q3 = q8(v.w, inv);
            g_EqT[k * KCB + i] = (q0 & 255) | ((q1 & 255) << 8) | ((q2 & 255) << 16) | ((q3 & 255) << 24);
        }
    }
}

// ---------------------------------------------------------------------------
// Kernel 2: int8 dp4a coarse GEMM + margin candidate collection.
// 512 threads = 16 token-groups(ty) x 32 code-lanes(tx); 8 tokens x 4 codes
// per thread; CODE_TILE=128 (4 tiles/CTA, QRANGE=512). smem ~97.5KB =>
// 2 CTAs/SM (32 warps). Grid = 256 token-tiles x 8 slices = 2048 CTAs
// (~33us each -> fine-grained tail). Tile-min via redux.sync.min.u32.
// ---------------------------------------------------------------------------
#define SM_X    0                     // int Xs[64][128]            32KB
#define SM_E    32768                 // int Es[2][64][128]         64KB
#define SM_MARG 98304                 // float marg[128]
#define SM_SX   98816                 // float sx[128]
#define SMEM_TOTAL 99328

__global__ __launch_bounds__(512, 2) void coarse_kernel() {
    extern __shared__ __align__(16) char smem[];
    const int tid = threadIdx.x;
    const int tx = tid & 31, ty = tid >> 5;            // 32 code lanes x 16 groups
    const int mb = (blockIdx.x >> 3) * TOK_TILE;       // token base
    const int cq = (blockIdx.x & 7) * QRANGE;          // code-slice base
    uint32_t sb = smem_to_u32(smem);
    int* Xs = reinterpret_cast<int*>(smem + SM_X);
    int* Es = reinterpret_cast<int*>(smem + SM_E);
    float* marg_s = reinterpret_cast<float*>(smem + SM_MARG);
    float* sx_s = reinterpret_cast<float*>(smem + SM_SX);

    if (tid < TOK_TILE) {
        float sx = g_sx[mb + tid];
        float lx = g_Lx[mb + tid];
        sx_s[tid] = sx;
        marg_s[tid] = token_margin(sx, lx, __uint_as_float(g_maxse_u), __uint_as_float(g_maxLe_u));
    }

    // X tile: 64 kchunks x 128 tokens = 2048 cp16 (4 per thread)
    #pragma unroll
    for (int k = 0; k < 4; k++) {
        int v = tid + k * 512;
        int row = v >> 5, ch = v & 31;
        cp_async16(sb + SM_X + (row * 128 + ch * 4) * 4,
                   g_XqT + (size_t)row * N_TOK + mb + ch * 4);
    }
    // E tile 0: 64 kchunks x 128 codes
    #pragma unroll
    for (int k = 0; k < 4; k++) {
        int v = tid + k * 512;
        int row = v >> 5, ch = v & 31;
        cp_async16(sb + SM_E + (row * 128 + ch * 4) * 4,
                   g_EqT + (size_t)row * KCB + cq + ch * 4);
    }
    cp_commit();
    cp_wait0();
    __syncthreads();

    float sxv[8], margv[8], runmin[8];
    #pragma unroll
    for (int i = 0; i < 8; i++) {
        sxv[i]   = sx_s[ty * 8 + i];
        margv[i] = marg_s[ty * 8 + i];
        runmin[i] = CUDART_INF_F;
    }

    for (int ct = 0; ct < N_CTILE; ct++) {
        const int cur = ct & 1;

        if (ct < N_CTILE - 1) {
            #pragma unroll
            for (int k = 0; k < 4; k++) {
                int v = tid + k * 512;
                int row = v >> 5, ch = v & 31;
                cp_async16(sb + SM_E + ((cur ^ 1) * 8192 + row * 128 + ch * 4) * 4,
                           g_EqT + (size_t)row * KCB + cq + (ct + 1) * CODE_TILE + ch * 4);
            }
            cp_commit();
        }

        int acc[8][4];
        #pragma unroll
        for (int i = 0; i < 8; i++)
            #pragma unroll
            for (int j = 0; j < 4; j++) acc[i][j] = 0;

        const int* eb = Es + cur * 8192;
        #pragma unroll 4
        for (int kc = 0; kc < NKCH; kc++) {
            int4 a0 = *reinterpret_cast<const int4*>(Xs + kc * 128 + ty * 8);
            int4 a1 = *reinterpret_cast<const int4*>(Xs + kc * 128 + ty * 8 + 4);
            int4 b0 = *reinterpret_cast<const int4*>(eb + kc * 128 + tx * 4);
            int aw[8] = {a0.x, a0.y, a0.z, a0.w, a1.x, a1.y, a1.z, a1.w};
            int bw[4] = {b0.x, b0.y, b0.z, b0.w};
            #pragma unroll
            for (int i = 0; i < 8; i++)
                #pragma unroll
                for (int j = 0; j < 4; j++)
                    dp4a(acc[i][j], aw[i], bw[j]);
        }

        // epilogue: s_hat, warp-wide tile-min via redux, running-min collection
        float2 sec4[4];
        #pragma unroll
        for (int j = 0; j < 4; j++)
            sec4[j] = __ldg(&g_sec[cq + ct * CODE_TILE + tx * 4 + j]);
        #pragma unroll
        for (int i = 0; i < 8; i++) {
            const float sx = sxv[i];
            float s[4];
            float tmin = CUDART_INF_F;
            #pragma unroll
            for (int j = 0; j < 4; j++) {
                s[j] = fmaf(sx * sec4[j].x, (float)acc[i][j], sec4[j].y);
                tmin = fminf(tmin, s[j]);
            }
            tmin = fdec(warp_min_u32(fenc(tmin)));   // min over all 32 code-lanes
            runmin[i] = fminf(runmin[i], tmin);
            const float th = runmin[i] + margv[i];
            bool any = false;
            #pragma unroll
            for (int j = 0; j < 4; j++) any |= (s[j] <= th);
            if (any) {
                const int token = mb + ty * 8 + i;
                #pragma unroll
                for (int j = 0; j < 4; j++) {
                    if (s[j] <= th) {
                        int code = cq + ct * CODE_TILE + tx * 4 + j;
                        int p = atomicAdd(&g_ncand[token], 1);
                        if (p < MAX_CAND) {
                            g_cand[token][p] = (unsigned short)code;
                            g_cand_s[token][p] = s[j];
                        }
                    }
                }
            }
        }

        if (ct < N_CTILE - 1) cp_wait0();
        __syncthreads();
    }
}

// ---------------------------------------------------------------------------
// Kernel 3: survivor-filtered exact rescore + gather + STE output + loss.
// One warp per token; dynamic slot loop over ceil(n/32) (MAX_CAND=256).
// Survivor filter: candidates with coarse s <= finalmin + marg — provably
// contains the exact argmin & ties. 1 survivor -> no dot products;
// else exact R2-chain d2 on survivors, lexicographic min.
// Output: lane owns 8 contiguous elements; vectorized stores (region is
// 4B-offset, so pattern is 32+64+128+32-bit). Per-element math is bit-exact;
// only the per-token loss summation ORDER changes (delta ~1e-7 relative).
// ---------------------------------------------------------------------------
#define NSLOT (MAX_CAND / 32)   // 8

__global__ void rescore_output_kernel(const float* __restrict__ X, const float* __restrict__ E,
                                      float* __restrict__ out_q, float* __restrict__ out_idx_f) {
    int token = (blockIdx.x * blockDim.x + threadIdx.x) >> 5;
    int lane = threadIdx.x & 31;
    if (token >= N_TOK) return;
    int n = g_ncand[token];
    float S = g_S[token];
    const float4* xr = reinterpret_cast<const float4*>(X + (size_t)token * DIM);

    int besti = 0x7fffffff;

    if (n <= MAX_CAND) {
        const int qmax = (n + 31) >> 5;      // warp-uniform
        float sc[NSLOT];
        int   cd[NSLOT];
        float fm = CUDART_INF_F;
        for (int q = 0; q < qmax; q++) {
            int idx = lane + q * 32;
            if (idx < n) { cd[q] = g_cand[token][idx]; sc[q] = g_cand_s[token][idx]; }
            else         { cd[q] = 0x7fffffff;         sc[q] = CUDART_INF_F; }
            fm = fminf(fm, sc[q]);
        }
        #pragma unroll
        for (int off = 16; off >= 1; off >>= 1)
            fm = fminf(fm, __shfl_xor_sync(0xffffffffu, fm, off));
        const float marg = token_margin(g_sx[token], g_Lx[token],
                                        __uint_as_float(g_maxse_u), __uint_as_float(g_maxLe_u));
        const float th = fm + marg;

        bool sv[NSLOT];
        int tot = 0;
        for (int q = 0; q < qmax; q++) {
            sv[q] = (sc[q] <= th);
            tot += __popc(__ballot_sync(0xffffffffu, sv[q]));
        }

        if (tot == 1) {
            int myc = 0x7fffffff;
            for (int q = 0; q < qmax; q++) if (sv[q]) myc = cd[q];
            #pragma unroll
            for (int off = 16; off >= 1; off >>= 1)
                myc = min(myc, __shfl_xor_sync(0xffffffffu, myc, off));
            besti = myc;
        } else {
            float bestv = CUDART_INF_F;
            for (int q = 0; q < qmax; q++) {
                if (sv[q]) {
                    const float4* er = reinterpret_cast<const float4*>(E + (size_t)cd[q] * DIM);
                    float m = 0.0f;
                    #pragma unroll 8
                    for (int k = 0; k < DIM / 4; k++) {
                        float4 x = xr[k], e = er[k];
                        m = fmaf(x.x, e.x, m); m = fmaf(x.y, e.y, m);
                        m = fmaf(x.z, e.z, m); m = fmaf(x.w, e.w, m);
                    }
                    float t = fmaf(-2.0f, m, S);
                    float d2 = __fadd_rn(t, g_c[cd[q]]);
                    if (d2 < bestv || (d2 == bestv && cd[q] < besti)) { bestv = d2; besti = cd[q]; }
                }
            }
            #pragma unroll
            for (int off = 16; off >= 1; off >>= 1) {
                float ov = __shfl_xor_sync(0xffffffffu, bestv, off);
                int   oi = __shfl_xor_sync(0xffffffffu, besti, off);
                if (ov < bestv || (ov == bestv && oi < besti)) { bestv = ov; besti = oi; }
            }
            besti = __shfl_sync(0xffffffffu, besti, 0);
        }
    } else {
        // overflow fallback: exact scan of all codes (probability ~0)
        float bestv = CUDART_INF_F;
        for (int code = lane; code < KCB; code += 32) {
            const float4* er = reinterpret_cast<const float4*>(E + (size_t)code * DIM);
            float m = 0.0f;
            #pragma unroll 8
            for (int k = 0; k < DIM / 4; k++) {
                float4 x = xr[k], e = er[k];
                m = fmaf(x.x, e.x, m); m = fmaf(x.y, e.y, m);
                m = fmaf(x.z, e.z, m); m = fmaf(x.w, e.w, m);
            }
            float t = fmaf(-2.0f, m, S);
            float d2 = __fadd_rn(t, g_c[code]);
            if (d2 < bestv || (d2 == bestv && code < besti)) { bestv = d2; besti = code; }
        }
        #pragma unroll
        for (int off = 16; off >= 1; off >>= 1) {
            float ov = __shfl_xor_sync(0xffffffffu, bestv, off);
            int   oi = __shfl_xor_sync(0xffffffffu, besti, off);
            if (ov < bestv || (ov == bestv && oi < besti)) { bestv = ov; besti = oi; }
        }
        besti = __shfl_sync(0xffffffffu, besti, 0);
    }

    // gather + straight-through + loss. Lane owns elements [lane*8, lane*8+8).
    // Per-element arithmetic identical to the validated R2 chain.
    const float4* er = reinterpret_cast<const float4*>(E + (size_t)besti * DIM);
    const int base = lane * 8;           // element index, 32B-aligned
    float4 x0 = xr[base / 4], x1 = xr[base / 4 + 1];
    float4 e0 = er[base / 4], e1 = er[base / 4 + 1];
    float xv[8] = {x0.x, x0.y, x0.z, x0.w, x1.x, x1.y, x1.z, x1.w};
    float ev[8] = {e0.x, e0.y, e0.z, e0.w, e1.x, e1.y, e1.z, e1.w};
    float ov[8];
    float ls = 0.0f;
    #pragma unroll
    for (int j = 0; j < 8; j++) {
        float d = __fadd_rn(ev[j], -xv[j]);
        ls = __fadd_rn(ls, __fmul_rn(d, d));
        ov[j] = __fadd_rn(xv[j], d);
    }
    float* qr = out_q + (size_t)token * DIM + base;   // byte addr ≡ 4 (mod 16)
    qr[0] = ov[0];
    float2 p12 = make_float2(ov[1], ov[2]);
    *reinterpret_cast<float2*>(qr + 1) = p12;          // 8B-aligned
    float4 p36 = make_float4(ov[3], ov[4], ov[5], ov[6]);
    *reinterpret_cast<float4*>(qr + 3) = p36;          // 16B-aligned
    qr[7] = ov[7];

    #pragma unroll
    for (int off = 16; off >= 1; off >>= 1)
        ls = __fadd_rn(ls, __shfl_xor_sync(0xffffffffu, ls, off));
    if (lane == 0) {
        g_loss[token] = ls;
        out_idx_f[token] = (float)besti;
    }
}

// ---------------------------------------------------------------------------
// Kernels 4+5: two-stage deterministic double-precision loss reduction.
// ---------------------------------------------------------------------------
__global__ void finalize1_kernel() {
    __shared__ double sh[256];
    int b = blockIdx.x;
    sh[threadIdx.x] = (double)g_loss[b * 256 + threadIdx.x];
    __syncthreads();
    for (int off = 128; off >= 1; off >>= 1) {
        if (threadIdx.x < off) sh[threadIdx.x] += sh[threadIdx.x + off];
        __syncthreads();
    }
    if (threadIdx.x == 0) g_part[b] = sh[0];
}
__global__ void finalize2_kernel(float* __restrict__ out) {
    __shared__ double sh[128];
    sh[threadIdx.x] = g_part[threadIdx.x];
    __syncthreads();
    for (int off = 64; off >= 1; off >>= 1) {
        if (threadIdx.x < off) sh[threadIdx.x] += sh[threadIdx.x + off];
        __syncthreads();
    }
    if (threadIdx.x == 0)
        out[0] = (float)(0.5 * sh[0] / ((double)N_TOK * (double)DIM));
}

// ---------------------------------------------------------------------------
extern "C" void kernel_launch(void* const* d_in, const int* in_sizes, int n_in,
                              void* d_out, int out_size) {
    const float* X = (const float*)d_in[0];   // embedding_tokens [N, D]
    const float* E = (const float*)d_in[1];   // embeddings       [K, D]
    float* out = (float*)d_out;
    float* out_q   = out + 1;
    float* out_idx = out + 1 + (size_t)N_TOK * DIM;

    static int smem_set = 0;
    if (!smem_set) {
        cudaFuncSetAttribute(coarse_kernel, cudaFuncAttributeMaxDynamicSharedMemorySize, SMEM_TOTAL);
        smem_set = 1;
    }

    prep_kernel<<<N_TOK / 256, 256>>>(X, E);
    coarse_kernel<<<(N_TOK / TOK_TILE) * N_QUART, 512, SMEM_TOTAL>>>();
    rescore_output_kernel<<<(N_TOK * 32) / 256, 256>>>(X, E, out_q, out_idx);
    finalize1_kernel<<<128, 256>>>();
    finalize2_kernel<<<1, 128>>>(out);
}

// round 15
// speedup vs baseline: 1.0435x; 1.0435x over previous
#include <cuda_runtime.h>
#include <math_constants.h>
#include <cstdint>

// Problem constants: B=16,T=2048,D=256,K=4096
#define N_TOK 32768
#define DIM   256
#define KCB   4096
#define NKCH  (DIM / 4)     // 64 packed int32 k-chunks per row

#define TOK_TILE  128
#define CODE_TILE 128
#define N_QUART   4                        // code-range quarters per token tile
#define QRANGE    (KCB / N_QUART)          // 1024 codes per CTA
#define N_CTILE   (QRANGE / CODE_TILE)     // 8 tiles per CTA
#define MAX_CAND  192

// ---------------- device scratch (no allocations allowed) -------------------
__device__ float  g_S[N_TOK];
__device__ float  g_c[KCB];
__device__ float2 g_sec[KCB];              // {-2*se, c} for coarse epilogue
__device__ float  g_loss[N_TOK];
__device__ double g_part[128];
__device__ float  g_sx[N_TOK], g_Lx[N_TOK];
__device__ unsigned g_maxse_u, g_maxLe_u;  // raw bits of positive floats (monotone)
__device__ __align__(16) int g_XqT[NKCH * N_TOK];   // [kchunk][token]  8MB
__device__ __align__(16) int g_EqT[NKCH * KCB];     // [kchunk][code]   1MB
__device__ unsigned short g_cand[N_TOK][MAX_CAND];  // 12MB
__device__ float  g_cand_s[N_TOK][MAX_CAND];        // 24MB coarse scores
__device__ int    g_ncand[N_TOK];

// ---------------- helpers ----------------------------------------------------
__device__ __forceinline__ uint32_t smem_to_u32(const void* p) {
    uint32_t a;
    asm("{ .reg .u64 t; cvta.to.shared.u64 t, %1; cvt.u32.u64 %0, t; }" : "=r"(a) : "l"(p));
    return a;
}
__device__ __forceinline__ void dp4a(int& acc, int a, int b) {
    asm("dp4a.s32.s32 %0, %1, %2, %0;" : "+r"(acc) : "r"(a), "r"(b));
}
__device__ __forceinline__ void cp_async16(uint32_t dst_smem, const void* src) {
    asm volatile("cp.async.cg.shared.global [%0], [%1], 16;" :: "r"(dst_smem), "l"(src) : "memory");
}
__device__ __forceinline__ void cp_commit() { asm volatile("cp.async.commit_group;" ::: "memory"); }
__device__ __forceinline__ void cp_wait0()  { asm volatile("cp.async.wait_group 0;"  ::: "memory"); }
__device__ __forceinline__ int q8(float v, float inv) {
    int q = __float2int_rn(v * inv);
    return max(-127, min(127, q));
}
// order-preserving encode for floats (any sign) -> u32
__device__ __forceinline__ uint32_t fenc(float f) {
    uint32_t u = __float_as_uint(f);
    return (u & 0x80000000u) ? ~u : (u | 0x80000000u);
}
__device__ __forceinline__ float fdec(uint32_t u) {
    uint32_t b = (u & 0x80000000u) ? (u & 0x7FFFFFFFu) : ~u;
    return __uint_as_float(b);
}
__device__ __forceinline__ uint32_t warp_min_u32(uint32_t v) {
    uint32_t r;
    asm volatile("redux.sync.min.u32 %0, %1, 0xffffffff;" : "=r"(r) : "r"(v));
    return r;
}
// rigorous per-token margin: 2*(int8 quant bound on 2m) + fp32 d2-chain slop
__device__ __forceinline__ float token_margin(float sx, float lx, float mse, float mle) {
    return 2.0f * (0.5f * sx * mle + 0.5f * mse * lx + 128.0f * sx * mse) + 3.0e-4f;
}

// ---------------------------------------------------------------------------
// Kernel 1: per-row exact-fp32 sums of squares (bit-matching R2 chain),
// per-row max/L1, int8 quantization into TRANSPOSED packed layout.
// Builds g_sec and the global maxima of se/Le (warp-reduce + atomicMax on raw
// positive-float bits; max is idempotent across graph replays => deterministic).
// ---------------------------------------------------------------------------
__global__ void prep_kernel(const float* __restrict__ X, const float* __restrict__ E) {
    int i = blockIdx.x * blockDim.x + threadIdx.x;
    if (i < N_TOK) {
        g_ncand[i] = 0;
        const float4* row = reinterpret_cast<const float4*>(X + (size_t)i * DIM);
        float s = 0.0f, mx = 0.0f, l1 = 0.0f;
        #pragma unroll 8
        for (int j = 0; j < DIM / 4; j++) {
            float4 v = row[j];
            s = __fadd_rn(s, __fmul_rn(v.x, v.x));
            s = __fadd_rn(s, __fmul_rn(v.y, v.y));
            s = __fadd_rn(s, __fmul_rn(v.z, v.z));
            s = __fadd_rn(s, __fmul_rn(v.w, v.w));
            float ax = fabsf(v.x), ay = fabsf(v.y), az = fabsf(v.z), aw = fabsf(v.w);
            mx = fmaxf(fmaxf(mx, ax), fmaxf(ay, fmaxf(az, aw)));
            l1 += ax + ay + az + aw;
        }
        g_S[i] = s;
        mx = fmaxf(mx, 1e-30f);
        float inv = 127.0f / mx;
        g_sx[i] = mx / 127.0f;
        g_Lx[i] = l1;
        #pragma unroll 8
        for (int k = 0; k < NKCH; k++) {
            float4 v = row[k];
            int q0 = q8(v.x, inv), q1 = q8(v.y, inv), q2 = q8(v.z, inv), q3 = q8(v.w, inv);
            g_XqT[k * N_TOK + i] = (q0 & 255) | ((q1 & 255) << 8) | ((q2 & 255) << 16) | ((q3 & 255) << 24);
        }
    }
    if (i < KCB) {
        const float4* row = reinterpret_cast<const float4*>(E + (size_t)i * DIM);
        float s = 0.0f, mx = 0.0f, l1 = 0.0f;
        #pragma unroll 8
        for (int j = 0; j < DIM / 4; j++) {
            float4 v = row[j];
            s = __fadd_rn(s, __fmul_rn(v.x, v.x));
            s = __fadd_rn(s, __fmul_rn(v.y, v.y));
            s = __fadd_rn(s, __fmul_rn(v.z, v.z));
            s = __fadd_rn(s, __fmul_rn(v.w, v.w));
            float ax = fabsf(v.x), ay = fabsf(v.y), az = fabsf(v.z), aw = fabsf(v.w);
            mx = fmaxf(fmaxf(mx, ax), fmaxf(ay, fmaxf(az, aw)));
            l1 += ax + ay + az + aw;
        }
        g_c[i] = s;
        mx = fmaxf(mx, 1e-30f);
        float inv = 127.0f / mx;
        float se = mx / 127.0f;
        g_sec[i] = make_float2(-2.0f * se, s);
        unsigned wse = __reduce_max_sync(0xffffffffu, __float_as_uint(se));
        unsigned wle = __reduce_max_sync(0xffffffffu, __float_as_uint(l1));
        if ((threadIdx.x & 31) == 0) {
            atomicMax(&g_maxse_u, wse);
            atomicMax(&g_maxLe_u, wle);
        }
        #pragma unroll 8
        for (int k = 0; k < NKCH; k++) {
            float4 v = row[k];
            int q0 = q8(v.x, inv), q1 = q8(v.y, inv), q2 = q8(v.z, inv), q3 = q8(v.w, inv);
            g_EqT[k * KCB + i] = (q0 & 255) | ((q1 & 255) << 8) | ((q2 & 255) << 16) | ((q3 & 255) << 24);
        }
    }
}

// ---------------------------------------------------------------------------
// Kernel 2: int8 dp4a coarse GEMM + margin candidate collection.
// 512 threads = 16 token-groups(ty) x 32 code-lanes(tx); 8 tokens x 4 codes
// per thread; CODE_TILE=128, QRANGE=1024 (8 tiles/CTA). smem ~97.5KB =>
// 2 CTAs/SM (32 warps). Grid = 256 token-tiles x 4 quarters = 1024 CTAs.
// Tile-min over a warp's 32 code-lanes via redux.sync.min.u32.
// ---------------------------------------------------------------------------
#define SM_X    0                     // int Xs[64][128]            32KB
#define SM_E    32768                 // int Es[2][64][128]         64KB
#define SM_MARG 98304                 // float marg[128]
#define SM_SX   98816                 // float sx[128]
#define SMEM_TOTAL 99328

__global__ __launch_bounds__(512, 2) void coarse_kernel() {
    extern __shared__ __align__(16) char smem[];
    const int tid = threadIdx.x;
    const int tx = tid & 31, ty = tid >> 5;            // 32 code lanes x 16 groups
    const int mb = (blockIdx.x >> 2) * TOK_TILE;       // token base
    const int cq = (blockIdx.x & 3) * QRANGE;          // code-quarter base
    uint32_t sb = smem_to_u32(smem);
    int* Xs = reinterpret_cast<int*>(smem + SM_X);
    int* Es = reinterpret_cast<int*>(smem + SM_E);
    float* marg_s = reinterpret_cast<float*>(smem + SM_MARG);
    float* sx_s = reinterpret_cast<float*>(smem + SM_SX);

    if (tid < TOK_TILE) {
        float sx = g_sx[mb + tid];
        float lx = g_Lx[mb + tid];
        sx_s[tid] = sx;
        marg_s[tid] = token_margin(sx, lx, __uint_as_float(g_maxse_u), __uint_as_float(g_maxLe_u));
    }

    // X tile: 64 kchunks x 128 tokens = 2048 cp16 (4 per thread)
    #pragma unroll
    for (int k = 0; k < 4; k++) {
        int v = tid + k * 512;
        int row = v >> 5, ch = v & 31;
        cp_async16(sb + SM_X + (row * 128 + ch * 4) * 4,
                   g_XqT + (size_t)row * N_TOK + mb + ch * 4);
    }
    // E tile 0: 64 kchunks x 128 codes
    #pragma unroll
    for (int k = 0; k < 4; k++) {
        int v = tid + k * 512;
        int row = v >> 5, ch = v & 31;
        cp_async16(sb + SM_E + (row * 128 + ch * 4) * 4,
                   g_EqT + (size_t)row * KCB + cq + ch * 4);
    }
    cp_commit();
    cp_wait0();
    __syncthreads();

    float sxv[8], margv[8], runmin[8];
    #pragma unroll
    for (int i = 0; i < 8; i++) {
        sxv[i]   = sx_s[ty * 8 + i];
        margv[i] = marg_s[ty * 8 + i];
        runmin[i] = CUDART_INF_F;
    }

    for (int ct = 0; ct < N_CTILE; ct++) {
        const int cur = ct & 1;

        if (ct < N_CTILE - 1) {
            #pragma unroll
            for (int k = 0; k < 4; k++) {
                int v = tid + k * 512;
                int row = v >> 5, ch = v & 31;
                cp_async16(sb + SM_E + ((cur ^ 1) * 8192 + row * 128 + ch * 4) * 4,
                           g_EqT + (size_t)row * KCB + cq + (ct + 1) * CODE_TILE + ch * 4);
            }
            cp_commit();
        }

        int acc[8][4];
        #pragma unroll
        for (int i = 0; i < 8; i++)
            #pragma unroll
            for (int j = 0; j < 4; j++) acc[i][j] = 0;

        const int* eb = Es + cur * 8192;
        #pragma unroll 4
        for (int kc = 0; kc < NKCH; kc++) {
            int4 a0 = *reinterpret_cast<const int4*>(Xs + kc * 128 + ty * 8);
            int4 a1 = *reinterpret_cast<const int4*>(Xs + kc * 128 + ty * 8 + 4);
            int4 b0 = *reinterpret_cast<const int4*>(eb + kc * 128 + tx * 4);
            int aw[8] = {a0.x, a0.y, a0.z, a0.w, a1.x, a1.y, a1.z, a1.w};
            int bw[4] = {b0.x, b0.y, b0.z, b0.w};
            #pragma unroll
            for (int i = 0; i < 8; i++)
                #pragma unroll
                for (int j = 0; j < 4; j++)
                    dp4a(acc[i][j], aw[i], bw[j]);
        }

        // epilogue: s_hat, warp-wide tile-min via redux, running-min collection
        float2 sec4[4];
        #pragma unroll
        for (int j = 0; j < 4; j++)
            sec4[j] = __ldg(&g_sec[cq + ct * CODE_TILE + tx * 4 + j]);
        #pragma unroll
        for (int i = 0; i < 8; i++) {
            const float sx = sxv[i];
            float s[4];
            float tmin = CUDART_INF_F;
            #pragma unroll
            for (int j = 0; j < 4; j++) {
                s[j] = fmaf(sx * sec4[j].x, (float)acc[i][j], sec4[j].y);
                tmin = fminf(tmin, s[j]);
            }
            tmin = fdec(warp_min_u32(fenc(tmin)));   // min over all 32 code-lanes
            runmin[i] = fminf(runmin[i], tmin);
            const float th = runmin[i] + margv[i];
            bool any = false;
            #pragma unroll
            for (int j = 0; j < 4; j++) any |= (s[j] <= th);
            if (any) {
                const int token = mb + ty * 8 + i;
                #pragma unroll
                for (int j = 0; j < 4; j++) {
                    if (s[j] <= th) {
                        int code = cq + ct * CODE_TILE + tx * 4 + j;
                        int p = atomicAdd(&g_ncand[token], 1);
                        if (p < MAX_CAND) {
                            g_cand[token][p] = (unsigned short)code;
                            g_cand_s[token][p] = s[j];
                        }
                    }
                }
            }
        }

        if (ct < N_CTILE - 1) cp_wait0();
        __syncthreads();
    }
}

// ---------------------------------------------------------------------------
// Kernel 3: survivor-filtered exact rescore + gather + STE output + loss.
// One warp per token; dynamic slot loop over ceil(n/32) (MAX_CAND=192).
// Survivor filter: candidates with coarse s <= finalmin + marg — provably
// contains the exact argmin & ties. 1 survivor -> no dot products;
// else exact R2-chain d2 on survivors, lexicographic min.
// Output: lane owns 8 contiguous elements; vectorized stores (region is
// 4B-offset => 32+64+128+32-bit pattern). Per-element math bit-exact; only
// the per-token loss summation ORDER differs (delta ~1e-7 relative).
// ---------------------------------------------------------------------------
#define NSLOT (MAX_CAND / 32)   // 6

__global__ void rescore_output_kernel(const float* __restrict__ X, const float* __restrict__ E,
                                      float* __restrict__ out_q, float* __restrict__ out_idx_f) {
    int token = (blockIdx.x * blockDim.x + threadIdx.x) >> 5;
    int lane = threadIdx.x & 31;
    if (token >= N_TOK) return;
    int n = g_ncand[token];
    float S = g_S[token];
    const float4* xr = reinterpret_cast<const float4*>(X + (size_t)token * DIM);

    int besti = 0x7fffffff;

    if (n <= MAX_CAND) {
        const int qmax = (n + 31) >> 5;      // warp-uniform
        float sc[NSLOT];
        int   cd[NSLOT];
        float fm = CUDART_INF_F;
        for (int q = 0; q < qmax; q++) {
            int idx = lane + q * 32;
            if (idx < n) { cd[q] = g_cand[token][idx]; sc[q] = g_cand_s[token][idx]; }
            else         { cd[q] = 0x7fffffff;         sc[q] = CUDART_INF_F; }
            fm = fminf(fm, sc[q]);
        }
        #pragma unroll
        for (int off = 16; off >= 1; off >>= 1)
            fm = fminf(fm, __shfl_xor_sync(0xffffffffu, fm, off));
        const float marg = token_margin(g_sx[token], g_Lx[token],
                                        __uint_as_float(g_maxse_u), __uint_as_float(g_maxLe_u));
        const float th = fm + marg;

        bool sv[NSLOT];
        int tot = 0;
        for (int q = 0; q < qmax; q++) {
            sv[q] = (sc[q] <= th);
            tot += __popc(__ballot_sync(0xffffffffu, sv[q]));
        }

        if (tot == 1) {
            int myc = 0x7fffffff;
            for (int q = 0; q < qmax; q++) if (sv[q]) myc = cd[q];
            #pragma unroll
            for (int off = 16; off >= 1; off >>= 1)
                myc = min(myc, __shfl_xor_sync(0xffffffffu, myc, off));
            besti = myc;
        } else {
            float bestv = CUDART_INF_F;
            for (int q = 0; q < qmax; q++) {
                if (sv[q]) {
                    const float4* er = reinterpret_cast<const float4*>(E + (size_t)cd[q] * DIM);
                    float m = 0.0f;
                    #pragma unroll 8
                    for (int k = 0; k < DIM / 4; k++) {
                        float4 x = xr[k], e = er[k];
                        m = fmaf(x.x, e.x, m); m = fmaf(x.y, e.y, m);
                        m = fmaf(x.z, e.z, m); m = fmaf(x.w, e.w, m);
                    }
                    float t = fmaf(-2.0f, m, S);
                    float d2 = __fadd_rn(t, g_c[cd[q]]);
                    if (d2 < bestv || (d2 == bestv && cd[q] < besti)) { bestv = d2; besti = cd[q]; }
                }
            }
            #pragma unroll
            for (int off = 16; off >= 1; off >>= 1) {
                float ov = __shfl_xor_sync(0xffffffffu, bestv, off);
                int   oi = __shfl_xor_sync(0xffffffffu, besti, off);
                if (ov < bestv || (ov == bestv && oi < besti)) { bestv = ov; besti = oi; }
            }
            besti = __shfl_sync(0xffffffffu, besti, 0);
        }
    } else {
        // overflow fallback: exact scan of all codes (probability ~0)
        float bestv = CUDART_INF_F;
        for (int code = lane; code < KCB; code += 32) {
            const float4* er = reinterpret_cast<const float4*>(E + (size_t)code * DIM);
            float m = 0.0f;
            #pragma unroll 8
            for (int k = 0; k < DIM / 4; k++) {
                float4 x = xr[k], e = er[k];
                m = fmaf(x.x, e.x, m); m = fmaf(x.y, e.y, m);
                m = fmaf(x.z, e.z, m); m = fmaf(x.w, e.w, m);
            }
            float t = fmaf(-2.0f, m, S);
            float d2 = __fadd_rn(t, g_c[code]);
            if (d2 < bestv || (d2 == bestv && code < besti)) { bestv = d2; besti = code; }
        }
        #pragma unroll
        for (int off = 16; off >= 1; off >>= 1) {
            float ov = __shfl_xor_sync(0xffffffffu, bestv, off);
            int   oi = __shfl_xor_sync(0xffffffffu, besti, off);
            if (ov < bestv || (ov == bestv && oi < besti)) { bestv = ov; besti = oi; }
        }
        besti = __shfl_sync(0xffffffffu, besti, 0);
    }

    // gather + straight-through + loss. Lane owns elements [lane*8, lane*8+8).
    // Per-element arithmetic identical to the validated R2 chain.
    const float4* er = reinterpret_cast<const float4*>(E + (size_t)besti * DIM);
    const int base = lane * 8;           // element index, 32B-aligned
    float4 x0 = xr[base / 4], x1 = xr[base / 4 + 1];
    float4 e0 = er[base / 4], e1 = er[base / 4 + 1];
    float xv[8] = {x0.x, x0.y, x0.z, x0.w, x1.x, x1.y, x1.z, x1.w};
    float ev[8] = {e0.x, e0.y, e0.z, e0.w, e1.x, e1.y, e1.z, e1.w};
    float ov[8];
    float ls = 0.0f;
    #pragma unroll
    for (int j = 0; j < 8; j++) {
        float d = __fadd_rn(ev[j], -xv[j]);
        ls = __fadd_rn(ls, __fmul_rn(d, d));
        ov[j] = __fadd_rn(xv[j], d);
    }
    float* qr = out_q + (size_t)token * DIM + base;   // byte addr ≡ 4 (mod 16)
    qr[0] = ov[0];
    float2 p12 = make_float2(ov[1], ov[2]);
    *reinterpret_cast<float2*>(qr + 1) = p12;          // 8B-aligned
    float4 p36 = make_float4(ov[3], ov[4], ov[5], ov[6]);
    *reinterpret_cast<float4*>(qr + 3) = p36;          // 16B-aligned
    qr[7] = ov[7];

    #pragma unroll
    for (int off = 16; off >= 1; off >>= 1)
        ls = __fadd_rn(ls, __shfl_xor_sync(0xffffffffu, ls, off));
    if (lane == 0) {
        g_loss[token] = ls;
        out_idx_f[token] = (float)besti;
    }
}

// ---------------------------------------------------------------------------
// Kernels 4+5: two-stage deterministic double-precision loss reduction.
// ---------------------------------------------------------------------------
__global__ void finalize1_kernel() {
    __shared__ double sh[256];
    int b = blockIdx.x;
    sh[threadIdx.x] = (double)g_loss[b * 256 + threadIdx.x];
    __syncthreads();
    for (int off = 128; off >= 1; off >>= 1) {
        if (threadIdx.x < off) sh[threadIdx.x] += sh[threadIdx.x + off];
        __syncthreads();
    }
    if (threadIdx.x == 0) g_part[b] = sh[0];
}
__global__ void finalize2_kernel(float* __restrict__ out) {
    __shared__ double sh[128];
    sh[threadIdx.x] = g_part[threadIdx.x];
    __syncthreads();
    for (int off = 64; off >= 1; off >>= 1) {
        if (threadIdx.x < off) sh[threadIdx.x] += sh[threadIdx.x + off];
        __syncthreads();
    }
    if (threadIdx.x == 0)
        out[0] = (float)(0.5 * sh[0] / ((double)N_TOK * (double)DIM));
}

// ---------------------------------------------------------------------------
extern "C" void kernel_launch(void* const* d_in, const int* in_sizes, int n_in,
                              void* d_out, int out_size) {
    const float* X = (const float*)d_in[0];   // embedding_tokens [N, D]
    const float* E = (const float*)d_in[1];   // embeddings       [K, D]
    float* out = (float*)d_out;
    float* out_q   = out + 1;
    float* out_idx = out + 1 + (size_t)N_TOK * DIM;

    static int smem_set = 0;
    if (!smem_set) {
        cudaFuncSetAttribute(coarse_kernel, cudaFuncAttributeMaxDynamicSharedMemorySize, SMEM_TOTAL);
        smem_set = 1;
    }

    prep_kernel<<<N_TOK / 256, 256>>>(X, E);
    coarse_kernel<<<(N_TOK / TOK_TILE) * N_QUART, 512, SMEM_TOTAL>>>();
    rescore_output_kernel<<<(N_TOK * 32) / 256, 256>>>(X, E, out_q, out_idx);
    finalize1_kernel<<<128, 256>>>();
    finalize2_kernel<<<1, 128>>>(out);
}